// round 8
// baseline (speedup 1.0000x reference)
#include <cuda_runtime.h>

#define NB      64
#define NT      1024
#define MAXLAG  256
#define NCHUNK  16         /* position-pair interleave chunks (global) */
#define NBY     8          /* blockIdx.y range; each block owns 2 chunks */
#define NTHR    512

// Scratch (device globals; allocation forbidden). Partials fully overwritten
// each launch. Counters self-reset -> deterministic across graph replays.
// Layout [b][L][chunk] so the finalizer reads 16 partials as 4x LDG.128.
__device__ float    g_msd_part[NB][MAXLAG][NCHUNK];
__device__ float    g_per_traj[NB];
__device__ unsigned g_cnt_traj[NB];
__device__ unsigned g_cnt_final;

// lengths declared int64 in the reference but JAX w/o x64 emits int32.
// Little-endian int64 -> every odd 32-bit word is 0; int32 -> word1 >= 512.
__device__ __forceinline__ int read_len(const int* __restrict__ p, int b)
{
    return (p[1] == 0) ? p[2 * b] : p[b];
}

#define FMA2(acc, s, e) \
    asm("fma.rn.f32x2 %0, %1, %2, %0;" : "+l"(acc) : "l"(s), "l"(e))
#define DIFF2(d, s, e) \
    asm("fma.rn.f32x2 %0, %1, %2, %3;" : "=l"(d) : "l"(s), "l"(NEG1), "l"(e))

// Block-wide sum over 512 threads (16 warps).
__device__ __forceinline__ float block_sum_512(float v, float* sbuf)
{
    #pragma unroll
    for (int o = 16; o > 0; o >>= 1)
        v += __shfl_down_sync(0xffffffffu, v, o);
    const int warp = threadIdx.x >> 5;
    if ((threadIdx.x & 31) == 0) sbuf[warp] = v;
    __syncthreads();
    if (threadIdx.x < 16) {
        v = sbuf[threadIdx.x];
        #pragma unroll
        for (int o = 8; o > 0; o >>= 1)
            v += __shfl_down_sync(0xffffu, v, o);
        if (threadIdx.x == 0) sbuf[0] = v;
    }
    __syncthreads();
    float r = sbuf[0];
    __syncthreads();
    return r;
}

// ---------------------------------------------------------------------------
// Fused kernel. grid = (NB, NBY), block = 512.
// Thread t: lag L = (t & 255) + 1, chunk = 2*blockIdx.y + (t >> 8).
// Phase 1: partial MSD sums over interleaved position pairs {2c,2c+1} mod 32.
// Phase 2 (last block per b): per-trajectory log-fit loss.
// Phase 3 (last finalizer): mean over trajectories.
// ---------------------------------------------------------------------------
__global__ __launch_bounds__(NTHR) void fused_kernel(
    const float* __restrict__ traj,
    const int*   __restrict__ lengths_raw,
    const float* __restrict__ alpha_pred,
    float*       __restrict__ out)
{
    __shared__ __align__(16) float2 y[NT];
    __shared__ float    sbuf[16];
    __shared__ unsigned s_flag;

    const int b     = blockIdx.x;
    const int t     = threadIdx.x;
    const int lt    = t & (MAXLAG - 1);
    const int L     = lt + 1;
    const int chunk = 2 * blockIdx.y + (t >> 8);

    // ---- stage trajectory into smem (one float4 per thread) -------------
    {
        const float4* src = reinterpret_cast<const float4*>(traj + (size_t)b * NT * 2);
        reinterpret_cast<float4*>(y)[t] = src[t];
    }
    const int len = read_len(lengths_raw, b);
    __syncthreads();

    const int bound = len - L;                 // valid positions p in [0,bound)

    // ---- Phase 1: MSD partials over pairs (2c,2c+1) stride 32 -----------
    const unsigned long long* y64  = reinterpret_cast<const unsigned long long*>(y);
    const ulonglong2*         y128 = reinterpret_cast<const ulonglong2*>(y);
    const unsigned long long NEG1 = 0xBF800000BF800000ULL;   // {-1.f,-1.f}

    unsigned long long acc0 = 0ULL, acc1 = 0ULL, acc2 = 0ULL, acc3 = 0ULL;

    int p = 2 * chunk;
    {
        const ulonglong2*         sp = y128 + chunk;     // p>>1
        const unsigned long long* ep = y64 + p + L;

        // hyper body: positions p..p+1, +32..33, +64..65, +96..97
        for (; p + 97 < bound; p += 128, sp += 64, ep += 128) {
            ulonglong2 s0 = sp[0];
            ulonglong2 s1 = sp[16];
            ulonglong2 s2 = sp[32];
            ulonglong2 s3 = sp[48];
            unsigned long long e0 = ep[0],  e1 = ep[1];
            unsigned long long e2 = ep[32], e3 = ep[33];
            unsigned long long e4 = ep[64], e5 = ep[65];
            unsigned long long e6 = ep[96], e7 = ep[97];
            unsigned long long d;
            DIFF2(d, s0.x, e0); FMA2(acc0, d, d);
            DIFF2(d, s0.y, e1); FMA2(acc1, d, d);
            DIFF2(d, s1.x, e2); FMA2(acc2, d, d);
            DIFF2(d, s1.y, e3); FMA2(acc3, d, d);
            DIFF2(d, s2.x, e4); FMA2(acc0, d, d);
            DIFF2(d, s2.y, e5); FMA2(acc1, d, d);
            DIFF2(d, s3.x, e6); FMA2(acc2, d, d);
            DIFF2(d, s3.y, e7); FMA2(acc3, d, d);
        }
        for (; p + 1 < bound; p += 32, sp += 16, ep += 32) {
            ulonglong2 s = sp[0];
            unsigned long long e0 = ep[0], e1 = ep[1];
            unsigned long long d;
            DIFF2(d, s.x, e0); FMA2(acc0, d, d);
            DIFF2(d, s.y, e1); FMA2(acc1, d, d);
        }
        if (p < bound) {
            unsigned long long s = y64[p];
            unsigned long long e = y64[p + L];
            unsigned long long d;
            DIFF2(d, s, e); FMA2(acc2, d, d);
        }
    }

    {
        unsigned long long m01, m23;
        asm("add.rn.f32x2 %0, %1, %2;" : "=l"(m01) : "l"(acc0), "l"(acc1));
        asm("add.rn.f32x2 %0, %1, %2;" : "=l"(m23) : "l"(acc2), "l"(acc3));
        asm("add.rn.f32x2 %0, %1, %2;" : "=l"(m01) : "l"(m01), "l"(m23));
        float cx, cy;
        asm("mov.b64 {%0, %1}, %2;" : "=f"(cx), "=f"(cy) : "l"(m01));
        g_msd_part[b][lt][chunk] = cx + cy;
    }

    // ---- elect finalizer block for this trajectory ----------------------
    __threadfence();
    __syncthreads();
    if (t == 0) s_flag = atomicAdd(&g_cnt_traj[b], 1u);
    __syncthreads();
    if (s_flag != NBY - 1) return;             // uniform per block

    // ---- Phase 2: per-trajectory loss -----------------------------------
    if (t == 0) g_cnt_traj[b] = 0u;            // reset for next replay

    float mask = 0.0f, resid = 0.0f, log_msd = 0.0f, log_lag = 0.0f, alpha = 0.0f;
    if (t < MAXLAG) {
        // 16 partials = 4 vector loads
        const float4* part = reinterpret_cast<const float4*>(g_msd_part[b][lt]);
        float4 q0 = part[0], q1 = part[1], q2 = part[2], q3 = part[3];
        float msd = ((q0.x + q0.y) + (q0.z + q0.w))
                  + ((q1.x + q1.y) + (q1.z + q1.w))
                  + ((q2.x + q2.y) + (q2.z + q2.w))
                  + ((q3.x + q3.y) + (q3.z + q3.w));
        const float count = fmaxf((float)(len - L), 1.0f);
        msd /= count;

        log_msd = logf(msd + 1e-8f);
        log_lag = logf((float)L);
        alpha   = alpha_pred[b];
        mask    = (len > L) ? 1.0f : 0.0f;
        resid   = log_msd - alpha * log_lag;
    }

    const float denom     = fmaxf(block_sum_512(mask, sbuf), 1.0f);
    const float intercept = block_sum_512(resid * mask, sbuf) / denom;

    float sq = 0.0f;
    if (t < MAXLAG) {
        const float err = alpha * log_lag + intercept - log_msd;
        sq = err * err * mask;
    }
    const float per_traj = block_sum_512(sq, sbuf) / denom;

    // ---- elect mean block ------------------------------------------------
    if (t == 0) {
        g_per_traj[b] = per_traj;
        __threadfence();
        s_flag = atomicAdd(&g_cnt_final, 1u);
    }
    __syncthreads();
    if (s_flag != NB - 1) return;

    // ---- Phase 3: mean over trajectories ---------------------------------
    if (t == 0) g_cnt_final = 0u;              // reset for next replay

    if (t < 64) {
        float v = g_per_traj[t];
        #pragma unroll
        for (int o = 16; o > 0; o >>= 1)
            v += __shfl_down_sync(0xffffffffu, v, o);
        if ((t & 31) == 0) sbuf[t >> 5] = v;
    }
    __syncthreads();
    if (t == 0) out[0] = (sbuf[0] + sbuf[1]) * (1.0f / (float)NB);
}

// ---------------------------------------------------------------------------
extern "C" void kernel_launch(void* const* d_in, const int* in_sizes, int n_in,
                              void* d_out, int out_size)
{
    const float* alpha       = (const float*)d_in[0];   // [64]
    const float* traj        = (const float*)d_in[1];   // [64,1024,2]
    const int*   lengths_raw = (const int*)d_in[2];     // [64] int32 or int64
    float* out = (float*)d_out;

    dim3 grid(NB, NBY);
    fused_kernel<<<grid, NTHR>>>(traj, lengths_raw, alpha, out);
}

// round 10
// speedup vs baseline: 1.1080x; 1.1080x over previous
#include <cuda_runtime.h>

#define NB      64
#define NT      1024
#define MAXLAG  256
#define NCHUNK  16
#define NTHR    256

// Scratch (device globals; allocation forbidden). Partials fully overwritten
// each launch. Counters self-reset -> deterministic across graph replays.
// Layout [b][L][chunk]: finalizer reads 16 partials as 4x LDG.128.
__device__ float    g_msd_part[NB][MAXLAG][NCHUNK];
__device__ float    g_per_traj[NB];
__device__ unsigned g_cnt_traj[NB];
__device__ unsigned g_cnt_final;

// lengths declared int64 in the reference but JAX w/o x64 emits int32.
// Little-endian int64 -> every odd 32-bit word is 0; int32 -> word1 >= 512.
__device__ __forceinline__ int read_len(const int* __restrict__ p, int b)
{
    return (p[1] == 0) ? p[2 * b] : p[b];
}

// Release+acquire fetch-add: orders this block's prior global writes before
// the increment, and makes all earlier releasers' writes visible to the
// winner -- replaces __threadfence() + atomicAdd on the critical chain.
__device__ __forceinline__ unsigned atom_add_acqrel(unsigned* addr, unsigned v)
{
    unsigned old;
    asm volatile("atom.acq_rel.gpu.global.add.u32 %0, [%1], %2;"
                 : "=r"(old) : "l"(addr), "r"(v) : "memory");
    return old;
}

#define FMA2(acc, s, e) \
    asm("fma.rn.f32x2 %0, %1, %2, %0;" : "+l"(acc) : "l"(s), "l"(e))
#define DIFF2(d, s, e) \
    asm("fma.rn.f32x2 %0, %1, %2, %3;" : "=l"(d) : "l"(s), "l"(NEG1), "l"(e))

// Single-pass block reduction of a float2 (8 warps / 256 threads).
__device__ __forceinline__ float2 block_sum2_256(float2 v, float2* sbuf)
{
    #pragma unroll
    for (int o = 16; o > 0; o >>= 1) {
        v.x += __shfl_down_sync(0xffffffffu, v.x, o);
        v.y += __shfl_down_sync(0xffffffffu, v.y, o);
    }
    const int warp = threadIdx.x >> 5;
    if ((threadIdx.x & 31) == 0) sbuf[warp] = v;
    __syncthreads();
    if (threadIdx.x < 8) {
        v = sbuf[threadIdx.x];
        #pragma unroll
        for (int o = 4; o > 0; o >>= 1) {
            v.x += __shfl_down_sync(0xffu, v.x, o);
            v.y += __shfl_down_sync(0xffu, v.y, o);
        }
        if (threadIdx.x == 0) sbuf[0] = v;
    }
    __syncthreads();
    return sbuf[0];
}

// ---------------------------------------------------------------------------
// Fused kernel. grid = (NB, NCHUNK), block = 256 (thread t <-> lag L = t+1).
// Phase 1: partial MSD over interleaved position pairs {2c,2c+1} stride 32.
// Phase 2 (last block per b): per-trajectory log-fit loss, one reduction.
// Phase 3 (last finalizer): mean over trajectories.
// ---------------------------------------------------------------------------
__global__ __launch_bounds__(NTHR) void fused_kernel(
    const float* __restrict__ traj,
    const int*   __restrict__ lengths_raw,
    const float* __restrict__ alpha_pred,
    float*       __restrict__ out)
{
    __shared__ __align__(16) float2 y[NT];
    __shared__ float2   sbuf[8];
    __shared__ unsigned s_flag;

    const int b     = blockIdx.x;
    const int chunk = blockIdx.y;
    const int t     = threadIdx.x;
    const int L     = t + 1;

    // ---- stage trajectory into smem; prefetch scalars -------------------
    {
        const float4* src = reinterpret_cast<const float4*>(traj + (size_t)b * NT * 2);
        float4* dst = reinterpret_cast<float4*>(y);
        #pragma unroll
        for (int i = t; i < NT / 2; i += NTHR)
            dst[i] = src[i];
    }
    const int   len   = read_len(lengths_raw, b);
    const float alpha = alpha_pred[b];          // prefetched for the tail
    __syncthreads();

    const int bound = len - L;                  // valid positions p in [0,bound)

    // ---- Phase 1: MSD partials ------------------------------------------
    const unsigned long long* y64  = reinterpret_cast<const unsigned long long*>(y);
    const ulonglong2*         y128 = reinterpret_cast<const ulonglong2*>(y);
    const unsigned long long NEG1 = 0xBF800000BF800000ULL;   // {-1.f,-1.f}

    unsigned long long acc0 = 0ULL, acc1 = 0ULL, acc2 = 0ULL, acc3 = 0ULL;

    int p = 2 * chunk;
    {
        const ulonglong2*         sp = y128 + chunk;     // p>>1
        const unsigned long long* ep = y64 + p + L;

        // hyper body: positions p..p+1, +32..33, +64..65, +96..97
        for (; p + 97 < bound; p += 128, sp += 64, ep += 128) {
            ulonglong2 s0 = sp[0];
            ulonglong2 s1 = sp[16];
            ulonglong2 s2 = sp[32];
            ulonglong2 s3 = sp[48];
            unsigned long long e0 = ep[0],  e1 = ep[1];
            unsigned long long e2 = ep[32], e3 = ep[33];
            unsigned long long e4 = ep[64], e5 = ep[65];
            unsigned long long e6 = ep[96], e7 = ep[97];
            unsigned long long d;
            DIFF2(d, s0.x, e0); FMA2(acc0, d, d);
            DIFF2(d, s0.y, e1); FMA2(acc1, d, d);
            DIFF2(d, s1.x, e2); FMA2(acc2, d, d);
            DIFF2(d, s1.y, e3); FMA2(acc3, d, d);
            DIFF2(d, s2.x, e4); FMA2(acc0, d, d);
            DIFF2(d, s2.y, e5); FMA2(acc1, d, d);
            DIFF2(d, s3.x, e6); FMA2(acc2, d, d);
            DIFF2(d, s3.y, e7); FMA2(acc3, d, d);
        }
        for (; p + 1 < bound; p += 32, sp += 16, ep += 32) {
            ulonglong2 s = sp[0];
            unsigned long long e0 = ep[0], e1 = ep[1];
            unsigned long long d;
            DIFF2(d, s.x, e0); FMA2(acc0, d, d);
            DIFF2(d, s.y, e1); FMA2(acc1, d, d);
        }
        if (p < bound) {
            unsigned long long s = y64[p];
            unsigned long long e = y64[p + L];
            unsigned long long d;
            DIFF2(d, s, e); FMA2(acc2, d, d);
        }
    }

    {
        unsigned long long m01, m23;
        asm("add.rn.f32x2 %0, %1, %2;" : "=l"(m01) : "l"(acc0), "l"(acc1));
        asm("add.rn.f32x2 %0, %1, %2;" : "=l"(m23) : "l"(acc2), "l"(acc3));
        asm("add.rn.f32x2 %0, %1, %2;" : "=l"(m01) : "l"(m01), "l"(m23));
        float cx, cy;
        asm("mov.b64 {%0, %1}, %2;" : "=f"(cx), "=f"(cy) : "l"(m01));
        g_msd_part[b][t][chunk] = cx + cy;
    }

    // ---- elect finalizer block for this trajectory (release+acquire) ----
    __syncthreads();                 // all STGs of this block issued
    if (t == 0) s_flag = atom_add_acqrel(&g_cnt_traj[b], 1u);
    __syncthreads();
    if (s_flag != NCHUNK - 1) return;            // uniform per block

    // ---- Phase 2: per-trajectory loss (single fused reduction) ----------
    if (t == 0) g_cnt_traj[b] = 0u;              // reset for next replay

    // 16 partials = 4 vector loads
    const float4* part = reinterpret_cast<const float4*>(g_msd_part[b][t]);
    float4 q0 = part[0], q1 = part[1], q2 = part[2], q3 = part[3];
    float msd = ((q0.x + q0.y) + (q0.z + q0.w))
              + ((q1.x + q1.y) + (q1.z + q1.w))
              + ((q2.x + q2.y) + (q2.z + q2.w))
              + ((q3.x + q3.y) + (q3.z + q3.w));
    msd /= fmaxf((float)bound, 1.0f);

    const float log_msd = logf(msd + 1e-8f);
    const float log_lag = logf((float)L);
    const float mask    = (len > L) ? 1.0f : 0.0f;
    const float resid   = (log_msd - alpha * log_lag) * mask;

    // denom = #lags with len > L = min(len-1, MAXLAG), clamped >= 1
    const int   dcnt  = (len - 1 < MAXLAG) ? (len - 1) : MAXLAG;
    const float denom = (float)((dcnt > 1) ? dcnt : 1);

    float2 s2 = block_sum2_256(make_float2(resid, resid * resid), sbuf);
    const float intercept = s2.x / denom;
    const float per_traj  = s2.y / denom - intercept * intercept;

    // ---- elect mean block (release+acquire) ------------------------------
    if (t == 0) {
        g_per_traj[b] = per_traj;
        s_flag = atom_add_acqrel(&g_cnt_final, 1u);
    }
    __syncthreads();
    if (s_flag != NB - 1) return;

    // ---- Phase 3: mean over trajectories ---------------------------------
    if (t == 0) g_cnt_final = 0u;                // reset for next replay

    if (t < 64) {
        float v = g_per_traj[t];
        #pragma unroll
        for (int o = 16; o > 0; o >>= 1)
            v += __shfl_down_sync(0xffffffffu, v, o);
        if ((t & 31) == 0) sbuf[t >> 5].x = v;
    }
    __syncthreads();
    if (t == 0) out[0] = (sbuf[0].x + sbuf[1].x) * (1.0f / (float)NB);
}

// ---------------------------------------------------------------------------
extern "C" void kernel_launch(void* const* d_in, const int* in_sizes, int n_in,
                              void* d_out, int out_size)
{
    const float* alpha       = (const float*)d_in[0];   // [64]
    const float* traj        = (const float*)d_in[1];   // [64,1024,2]
    const int*   lengths_raw = (const int*)d_in[2];     // [64] int32 or int64
    float* out = (float*)d_out;

    dim3 grid(NB, NCHUNK);
    fused_kernel<<<grid, NTHR>>>(traj, lengths_raw, alpha, out);
}